// round 16
// baseline (speedup 1.0000x reference)
#include <cuda_runtime.h>
#include <cstdint>

// Fixed shapes: B=8, H=W=512
#define BB 8
#define NN (512*512)          // 262144 pixels per row
#define PP (BB*NN)
#define THREADS 1024          // one CTA per SM -> 128-block grid is ONE wave
#define CTILE 16384           // px per block
#define BLKX (NN/CTILE)       // 16 blocks per row; grid 128 < 148 SMs
#define NB 2048               // 11-bit digit bins
#define SH1 21                // digit1 = key >> 21           (11 bits)
#define SH2 10                // digit2 = (key >> 10) & 2047  (11 bits)
#define SCAP 3072             // per-block smem candidate stage
#define OVCAP 32768           // per-row global overflow list
#define EQCAP 4096            // per-row global tie list

// ---------------- device scratch (zero-initialized at load; kernel restores
// the all-zero invariant on everything it consumes, for graph replays) -------
__device__ uint32_t g_keys[PP];       // 8 MB
__device__ uint32_t g_pl3[PP];        // 8 MB  loss3, target in sign bit
__device__ uint32_t g_hist[BB*NB];    // zero-invariant (digit1 hist, then digit2)
__device__ uint32_t g_sel1[BB];
__device__ uint32_t g_thr[BB];
__device__ int      g_kneed[BB];
__device__ int      g_eqcount[BB];    // zero-invariant
__device__ uint32_t g_eqkey[BB*EQCAP];
__device__ uint32_t g_eqidx[BB*EQCAP];
__device__ int      g_ovcount[BB];    // zero-invariant
__device__ uint32_t g_ovkey[BB*OVCAP];
__device__ uint32_t g_ovpl [BB*OVCAP];
__device__ uint32_t g_ovidx[BB*OVCAP];
__device__ int      g_done1[BB];      // zero-invariant tickets
__device__ int      g_done2[BB];
__device__ int      g_done3[BB];
__device__ int      g_flag1[BB];      // zero-invariant phase flags
__device__ int      g_flag2[BB];
__device__ int      g_rows_done;
__device__ double   g_sum_l3;         // zero-invariant
__device__ unsigned long long g_sum_tsel;
__device__ unsigned long long g_ttotal;

__device__ __forceinline__ uint32_t f2mono(float f) {
    uint32_t u = __float_as_uint(f);
    return (u & 0x80000000u) ? ~u : (u | 0x80000000u);
}

// Robust scalar read (f32 vs f64 sniff; true values are in (0,1)).
__device__ __forceinline__ double read_scalar(const void* p) {
    float f = *(const float*)p;
    if (f > 1e-6f && f < 1.0f) return (double)f;
    return *(const double*)p;
}

// 2-class softmax primitives: p0, p1, lp0=log p0, d = x0-x1.  (3 MUFU)
__device__ __forceinline__ void sm2f(float x0, float x1,
                                     float& p0, float& p1, float& lp0, float& d) {
    d = x0 - x1;
    float t = __expf(fminf(-d, 80.0f));
    p0 = __fdividef(1.0f, 1.0f + t);
    p1 = t * p0;
    lp0 = __logf(p0);
}

// focal via identities (1-p1=p0, 1-p0=p1, lp1=lp0-d)
__device__ __forceinline__ float focal(float tf, float p0, float p1, float lp0, float d) {
    float a = p0 * p0, b = p1 * p1;
    float c = fmaf(tf, a - b, b);
    return fmaf(tf * a, d, -lp0 * c);
}

__device__ __forceinline__ void pixel_loss(float a1, float c1, float a2, float c2,
                                           float a3, float c3, int t,
                                           float kdw, float w,
                                           float& loss, float& l3) {
    float p10, p11, lp10, d1; sm2f(a1, c1, p10, p11, lp10, d1);
    float p20, p21, lp20, d2; sm2f(a2, c2, p20, p21, lp20, d2);
    float p30, p31, lp30, d3; sm2f(a3, c3, p30, p31, lp30, d3);
    float tf = (float)t;
    float l1 = focal(tf, p10, p11, lp10, d1);
    float l2 = focal(tf, p20, p21, lp20, d2);
    l3       = focal(tf, p30, p31, lp30, d3);
    float kdl = (p10 - p20) * (d1 - d2);   // kdl12 + kdl21, exact identity
    loss = w * (l1 + l2 + l3) + kdw * kdl;
}

// 256-thread scan over NB bins of h (reads + zeroes); selecting thread writes.
__device__ __forceinline__ void scan_select(uint32_t* h, unsigned kneed,
                                            unsigned* ss, int tid,
                                            uint32_t* out_bin, int* out_rem) {
    unsigned local[NB/256];
    unsigned lsum = 0;
    if (tid < 256) {
#pragma unroll
        for (int i = 0; i < NB/256; i++) {
            local[i] = __ldcg(&h[tid * (NB/256) + i]);
            lsum += local[i];
            h[tid * (NB/256) + i] = 0u;       // restore zero-invariant
        }
        ss[tid] = lsum;
    }
    __syncthreads();
    for (int off = 1; off < 256; off <<= 1) {
        unsigned n = (tid >= off && tid < 256) ? ss[tid - off] : 0u;
        __syncthreads();
        if (tid < 256) ss[tid] += n;
        __syncthreads();
    }
    if (tid < 256) {
        unsigned incl = ss[tid];
        unsigned excl = incl - lsum;
        if (excl < kneed && kneed <= incl) {
            unsigned cum = excl;
#pragma unroll
            for (int i = 0; i < NB/256; i++) {
                if (cum + local[i] >= kneed) {
                    *out_bin = (uint32_t)(tid * (NB/256) + i);
                    *out_rem = (int)(kneed - cum);
                    break;
                }
                cum += local[i];
            }
        }
    }
    __syncthreads();
}

// ---------------- THE kernel: all phases fused, smem-resident candidates ----
__global__ void __launch_bounds__(THREADS, 1)
k_all(const float* __restrict__ in1, const float* __restrict__ in2,
      const float* __restrict__ in3, const int* __restrict__ tgt,
      const void* __restrict__ kdw_p, const void* __restrict__ forget_p,
      float* __restrict__ out)
{
    __shared__ uint32_t sh[NB];           // 8 KB: digit hist
    __shared__ uint32_t ckey[SCAP];       // 12 KB: candidates (reused for ties)
    __shared__ uint32_t cpl [SCAP];       // 12 KB
    __shared__ uint32_t cidx[SCAP];       // 12 KB
    __shared__ unsigned ss[256];
    __shared__ double sd[32];
    __shared__ int    si[32];
    __shared__ int swt[32];
    __shared__ int s_last, s_cnt, s_c;
    __shared__ uint32_t s_sel2; __shared__ int s_rem2;

    int tid = threadIdx.x;
    const int row = blockIdx.y;
    for (int i = tid; i < NB; i += THREADS) sh[i] = 0u;
    __syncthreads();

    // ======================= PHASE 1: math + digit1 hist =====================
    const float kdw = (float)read_scalar(kdw_p);
    const float w   = 1.0f - kdw;

    const float4* b1a = (const float4*)(in1 + (size_t)row * 2 * NN);
    const float4* b1c = (const float4*)(in1 + (size_t)row * 2 * NN + NN);
    const float4* b2a = (const float4*)(in2 + (size_t)row * 2 * NN);
    const float4* b2c = (const float4*)(in2 + (size_t)row * 2 * NN + NN);
    const float4* b3a = (const float4*)(in3 + (size_t)row * 2 * NN);
    const float4* b3c = (const float4*)(in3 + (size_t)row * 2 * NN + NN);
    const int4*   bt  = (const int4*)(tgt + (size_t)row * NN);
    uint4* kout = (uint4*)(g_keys + (size_t)row * NN);
    uint4* pout = (uint4*)(g_pl3  + (size_t)row * NN);

    int tcnt = 0;

#pragma unroll 1
    for (int g = 0; g < 4; g++) {
        int vi = (blockIdx.x * CTILE + g * (THREADS*4)) / 4 + tid;
        float4 A1 = b1a[vi], C1 = b1c[vi];
        float4 A2 = b2a[vi], C2 = b2c[vi];
        float4 A3 = b3a[vi], C3 = b3c[vi];
        int4   T  = bt[vi];

        float ls0, ls1, ls2, ls3, l30, l31, l32, l33;
        pixel_loss(A1.x, C1.x, A2.x, C2.x, A3.x, C3.x, T.x, kdw, w, ls0, l30);
        pixel_loss(A1.y, C1.y, A2.y, C2.y, A3.y, C3.y, T.y, kdw, w, ls1, l31);
        pixel_loss(A1.z, C1.z, A2.z, C2.z, A3.z, C3.z, T.z, kdw, w, ls2, l32);
        pixel_loss(A1.w, C1.w, A2.w, C2.w, A3.w, C3.w, T.w, kdw, w, ls3, l33);

        uint4 K = make_uint4(f2mono(ls0), f2mono(ls1), f2mono(ls2), f2mono(ls3));
        kout[vi] = K;
        uint4 P = make_uint4(__float_as_uint(l30) | ((uint32_t)T.x << 31),
                             __float_as_uint(l31) | ((uint32_t)T.y << 31),
                             __float_as_uint(l32) | ((uint32_t)T.z << 31),
                             __float_as_uint(l33) | ((uint32_t)T.w << 31));
        pout[vi] = P;

        atomicAdd(&sh[K.x >> SH1], 1u);
        atomicAdd(&sh[K.y >> SH1], 1u);
        atomicAdd(&sh[K.z >> SH1], 1u);
        atomicAdd(&sh[K.w >> SH1], 1u);
        tcnt += T.x + T.y + T.z + T.w;
    }
    __syncthreads();
    for (int i = tid; i < NB; i += THREADS) {
        uint32_t v = sh[i];
        if (v) atomicAdd(&g_hist[row * NB + i], v);
    }

#pragma unroll
    for (int o = 16; o; o >>= 1) tcnt += __shfl_down_sync(0xffffffffu, tcnt, o);
    if ((tid & 31) == 0) swt[tid >> 5] = tcnt;
    __syncthreads();
    if (tid == 0) {
        int s = 0;
#pragma unroll
        for (int i = 0; i < 32; i++) s += swt[i];
        atomicAdd(&g_ttotal, (unsigned long long)s);
        s_cnt = 0;                             // candidate counter for phase 2
    }

    // ---- digit1 select by the last-arriving block of this row ----
    __threadfence();
    if (tid == 0) s_last = (atomicAdd(&g_done1[row], 1) == BLKX - 1);
    __syncthreads();
    if (s_last) {
        if (tid == 0) g_done1[row] = 0;
        double rem = 1.0 - read_scalar(forget_p);
        unsigned kneed = (unsigned)(rem * (double)NN);
        scan_select(g_hist + row * NB, kneed, ss, tid, &g_sel1[row], &g_kneed[row]);
        __threadfence();
        if (tid == 0) atomicExch(&g_flag1[row], 1);
    }
    // ---- per-row barrier 1 (all blocks resident) ----
    if (tid == 0) { while (atomicAdd(&g_flag1[row], 0) == 0) __nanosleep(128); }
    __syncthreads();
    uint32_t sel1 = __ldcg(&g_sel1[row]);

    // ===== PHASE 2: bulk below-sum + smem candidate stage + digit2 hist ======
    const uint4* keysv = (const uint4*)(g_keys + (size_t)row * NN);
    const uint4* pl3v  = (const uint4*)(g_pl3  + (size_t)row * NN);
    int vbase = blockIdx.x * (CTILE/4) + tid;

    double sld = 0.0;
    int    st = 0;

#pragma unroll 1
    for (int h2 = 0; h2 < 2; h2++) {
        // front-batch 2 key + 2 payload vectors (MLP=4, L2-hot)
        uint4 K0 = keysv[vbase + (2*h2)   * THREADS];
        uint4 P0 = pl3v [vbase + (2*h2)   * THREADS];
        uint4 K1 = keysv[vbase + (2*h2+1) * THREADS];
        uint4 P1 = pl3v [vbase + (2*h2+1) * THREADS];
        uint32_t ks[8] = {K0.x,K0.y,K0.z,K0.w, K1.x,K1.y,K1.z,K1.w};
        uint32_t ps[8] = {P0.x,P0.y,P0.z,P0.w, P1.x,P1.y,P1.z,P1.w};
        float sl = 0.0f;
#pragma unroll
        for (int j = 0; j < 8; j++) {
            uint32_t d1 = ks[j] >> SH1;
            if (d1 < sel1) {
                sl += __uint_as_float(ps[j] & 0x7fffffffu);
                st += (int)(ps[j] >> 31);
            } else if (d1 == sel1) {
                int vidx = vbase + (2*h2 + (j >> 2)) * THREADS;
                uint32_t pidx = (uint32_t)(vidx * 4 + (j & 3));
                int p = atomicAdd(&s_cnt, 1);
                if (p < SCAP) {
                    ckey[p] = ks[j]; cpl[p] = ps[j]; cidx[p] = pidx;
                } else {                       // overflow (≈ never)
                    int gp = atomicAdd(&g_ovcount[row], 1);
                    if (gp < OVCAP) {
                        g_ovkey[row * OVCAP + gp] = ks[j];
                        g_ovpl [row * OVCAP + gp] = ps[j];
                        g_ovidx[row * OVCAP + gp] = pidx;
                    }
                }
                atomicAdd(&g_hist[row * NB + ((ks[j] >> SH2) & (NB-1))], 1u);
            }
        }
        sld += (double)sl;
    }
#pragma unroll
    for (int o = 16; o; o >>= 1) {
        sld += __shfl_down_sync(0xffffffffu, sld, o);
        st  += __shfl_down_sync(0xffffffffu, st, o);
    }
    if ((tid & 31) == 0) { sd[tid >> 5] = sld; si[tid >> 5] = st; }
    __syncthreads();
    if (tid == 0) {
        double S = 0.0; int Ti = 0;
#pragma unroll
        for (int i = 0; i < 32; i++) { S += sd[i]; Ti += si[i]; }
        atomicAdd(&g_sum_l3, S);
        atomicAdd(&g_sum_tsel, (unsigned long long)Ti);
    }

    // ---- digit2 select by the last-arriving block of this row ----
    __threadfence();
    if (tid == 0) s_last = (atomicAdd(&g_done2[row], 1) == BLKX - 1);
    __syncthreads();
    if (s_last) {
        if (tid == 0) { g_done2[row] = 0; s_sel2 = 0; s_rem2 = 0; }
        __syncthreads();
        unsigned kneed1 = (unsigned)g_kneed[row];
        scan_select(g_hist + row * NB, kneed1, ss, tid, &s_sel2, &s_rem2);
        if (tid == 0) {
            g_thr[row]   = ((sel1 << 11) | s_sel2) << SH2;
            g_kneed[row] = s_rem2;
            __threadfence();
            atomicExch(&g_flag2[row], 1);
        }
    }
    // ---- per-row barrier 2 ----
    if (tid == 0) { while (atomicAdd(&g_flag2[row], 0) == 0) __nanosleep(128); }
    __syncthreads();
    uint32_t thr = __ldcg(&g_thr[row]);
    uint32_t pfx22 = thr >> SH2;

    // ===== PHASE 3: scan OWN smem candidates (zero memory traffic) ===========
    int cnt = min(s_cnt, SCAP);
    double sl2 = 0.0;
    int    st2 = 0;
    for (int i = tid; i < cnt; i += THREADS) {
        uint32_t k = ckey[i];
        if (k < thr) {
            uint32_t p = cpl[i];
            sl2 += (double)__uint_as_float(p & 0x7fffffffu);
            st2 += (int)(p >> 31);
        } else if ((k >> SH2) == pfx22) {      // tie bin (~tens per row)
            int p = atomicAdd(&g_eqcount[row], 1);
            if (p < EQCAP) {
                g_eqkey[row * EQCAP + p] = k;
                g_eqidx[row * EQCAP + p] = cidx[i];
            }
        }
    }
#pragma unroll
    for (int o = 16; o; o >>= 1) {
        sl2 += __shfl_down_sync(0xffffffffu, sl2, o);
        st2 += __shfl_down_sync(0xffffffffu, st2, o);
    }
    if ((tid & 31) == 0) { sd[tid >> 5] = sl2; si[tid >> 5] = st2; }
    __syncthreads();
    if (tid == 0) {
        double S = 0.0; int Ti = 0;
#pragma unroll
        for (int i = 0; i < 32; i++) { S += sd[i]; Ti += si[i]; }
        atomicAdd(&g_sum_l3, S);
        atomicAdd(&g_sum_tsel, (unsigned long long)Ti);
    }

    // ---- last block of this row: overflow + tie resolve + maybe output ------
    __threadfence();
    if (tid == 0) s_last = (atomicAdd(&g_done3[row], 1) == BLKX - 1);
    __syncthreads();
    if (!s_last) return;

    // process overflow list (usually empty)
    int ovc = min(__ldcg(&g_ovcount[row]), OVCAP);
    double sl3 = 0.0;
    int    st3 = 0;
    for (int i = tid; i < ovc; i += THREADS) {
        uint32_t k = __ldcg(&g_ovkey[row * OVCAP + i]);
        if (k < thr) {
            uint32_t p = __ldcg(&g_ovpl[row * OVCAP + i]);
            sl3 += (double)__uint_as_float(p & 0x7fffffffu);
            st3 += (int)(p >> 31);
        } else if ((k >> SH2) == pfx22) {
            int p = atomicAdd(&g_eqcount[row], 1);
            if (p < EQCAP) {
                g_eqkey[row * EQCAP + p] = k;
                g_eqidx[row * EQCAP + p] = __ldcg(&g_ovidx[row * OVCAP + i]);
            }
        }
    }
    __syncthreads();

    // broadcast tie count BEFORE resetting (race-fix discipline)
    if (tid == 0) s_c = min(__ldcg(&g_eqcount[row]), min(EQCAP, SCAP));
    __syncthreads();
    int c = s_c;
    if (tid == 0) {
        g_done3[row] = 0; g_eqcount[row] = 0; g_ovcount[row] = 0;
        g_flag1[row] = 0; g_flag2[row] = 0;
    }
    int kneed2 = g_kneed[row];

    // reuse candidate smem arrays for the tie list
    for (int i = tid; i < c; i += THREADS) {
        ckey[i] = __ldcg(&g_eqkey[row * EQCAP + i]);
        cidx[i] = __ldcg(&g_eqidx[row * EQCAP + i]);
    }
    __syncthreads();

    // exact rank-select by (key, idx) — stable-argsort equivalent
    for (int j = tid; j < c; j += THREADS) {
        uint32_t kj = ckey[j], ij = cidx[j];
        int rank = 0;
        for (int q = 0; q < c; q++) {
            uint32_t kq = ckey[q], iq = cidx[q];
            rank += (kq < kj || (kq == kj && iq < ij)) ? 1 : 0;
        }
        if (rank < kneed2) {
            uint32_t p = __ldcg(&g_pl3[(size_t)row * NN + ij]);
            sl3 += (double)__uint_as_float(p & 0x7fffffffu);
            st3 += (int)(p >> 31);
        }
    }
#pragma unroll
    for (int o = 16; o; o >>= 1) {
        sl3 += __shfl_down_sync(0xffffffffu, sl3, o);
        st3 += __shfl_down_sync(0xffffffffu, st3, o);
    }
    if ((tid & 31) == 0) { sd[tid >> 5] = sl3; si[tid >> 5] = st3; }
    __syncthreads();
    if (tid != 0) return;

    double S = 0.0; int Ti = 0;
#pragma unroll
    for (int i = 0; i < 32; i++) { S += sd[i]; Ti += si[i]; }
    atomicAdd(&g_sum_l3, S);
    atomicAdd(&g_sum_tsel, (unsigned long long)Ti);

    __threadfence();
    if (atomicAdd(&g_rows_done, 1) == BB - 1) {
        double sl = atomicAdd(&g_sum_l3, 0.0);
        unsigned long long ts = atomicAdd(&g_sum_tsel, 0ull);
        unsigned long long tt = atomicAdd(&g_ttotal, 0ull);
        double rem = 1.0 - read_scalar(forget_p);
        long long num_rem = (long long)(rem * (double)NN);
        double denom = (double)BB * (double)num_rem;
        out[0] = (float)(sl / denom);
        out[1] = (float)((double)ts / (double)tt);
        // restore zero-invariant for graph replays
        g_rows_done = 0;
        g_sum_l3    = 0.0;
        g_sum_tsel  = 0ull;
        g_ttotal    = 0ull;
    }
}

// ---------------- host entry ----------------
extern "C" void kernel_launch(void* const* d_in, const int* in_sizes, int n_in,
                              void* d_out, int out_size) {
    const float* in1    = (const float*)d_in[0];
    const float* in2    = (const float*)d_in[1];
    const float* in3    = (const float*)d_in[2];
    const int*   tgt    = (const int*)d_in[3];
    const void*  forget = d_in[4];
    const void*  kdw    = d_in[5];
    float* out = (float*)d_out;

    k_all<<<dim3(BLKX, BB), THREADS>>>(in1, in2, in3, tgt, kdw, forget, out);

    (void)in_sizes; (void)n_in; (void)out_size;
}

// round 17
// speedup vs baseline: 1.1963x; 1.1963x over previous
#include <cuda_runtime.h>
#include <cstdint>

// Fixed shapes: B=8, H=W=512
#define BB 8
#define NN (512*512)          // 262144 pixels per row
#define PP (BB*NN)
#define THREADS 1024          // one CTA per SM -> 128-block grid is ONE wave
#define CTILE 16384           // px per block
#define BLKX (NN/CTILE)       // 16 blocks per row; grid 128 < 148 SMs
#define NB 2048               // 11-bit digit bins
#define SH1 21                // digit1 = key >> 21           (11 bits)
#define SH2 10                // digit2 = (key >> 10) & 2047  (11 bits)
#define EQCAP 4096
#define PAD 32                // 128-byte ticket padding (L2 hash pair-collision)

// ---------------- device scratch (zero-initialized at load; kernel restores
// the all-zero invariant on everything it consumes, for graph replays) -------
__device__ uint32_t g_keys[PP];        // 8 MB
__device__ uint32_t g_pl3[PP];         // 8 MB  loss3, target in sign bit
__device__ uint32_t g_hist1[BB*NB];    // digit1 hist, zero-invariant
__device__ uint32_t g_hist2[BB*NB];    // digit2 hist, zero-invariant
__device__ int      g_eqcount[BB];     // zero-invariant
__device__ uint32_t g_eqkey[BB*EQCAP];
__device__ uint32_t g_eqidx[BB*EQCAP];
__device__ int      g_done1[BB*PAD];   // zero-invariant tickets (padded)
__device__ int      g_done2[BB*PAD];
__device__ int      g_done3[BB*PAD];
__device__ int      g_rows_done;
__device__ double   g_sum_l3;          // zero-invariant
__device__ unsigned long long g_sum_tsel;
__device__ unsigned long long g_ttotal;

__device__ __forceinline__ uint32_t f2mono(float f) {
    uint32_t u = __float_as_uint(f);
    return (u & 0x80000000u) ? ~u : (u | 0x80000000u);
}

// Robust scalar read (f32 vs f64 sniff; true values are in (0,1)).
__device__ __forceinline__ double read_scalar(const void* p) {
    float f = *(const float*)p;
    if (f > 1e-6f && f < 1.0f) return (double)f;
    return *(const double*)p;
}

// 2-class softmax primitives: p0, p1, lp0=log p0, d = x0-x1.  (3 MUFU)
__device__ __forceinline__ void sm2f(float x0, float x1,
                                     float& p0, float& p1, float& lp0, float& d) {
    d = x0 - x1;
    float t = __expf(fminf(-d, 80.0f));
    p0 = __fdividef(1.0f, 1.0f + t);
    p1 = t * p0;
    lp0 = __logf(p0);
}

// focal via identities (1-p1=p0, 1-p0=p1, lp1=lp0-d)
__device__ __forceinline__ float focal(float tf, float p0, float p1, float lp0, float d) {
    float a = p0 * p0, b = p1 * p1;
    float c = fmaf(tf, a - b, b);
    return fmaf(tf * a, d, -lp0 * c);
}

__device__ __forceinline__ void pixel_loss(float a1, float c1, float a2, float c2,
                                           float a3, float c3, int t,
                                           float kdw, float w,
                                           float& loss, float& l3) {
    float p10, p11, lp10, d1; sm2f(a1, c1, p10, p11, lp10, d1);
    float p20, p21, lp20, d2; sm2f(a2, c2, p20, p21, lp20, d2);
    float p30, p31, lp30, d3; sm2f(a3, c3, p30, p31, lp30, d3);
    float tf = (float)t;
    float l1 = focal(tf, p10, p11, lp10, d1);
    float l2 = focal(tf, p20, p21, lp20, d2);
    l3       = focal(tf, p30, p31, lp30, d3);
    float kdl = (p10 - p20) * (d1 - d2);   // kdl12 + kdl21, exact identity
    loss = w * (l1 + l2 + l3) + kdw * kdl;
}

// READ-ONLY 256-thread scan over NB bins; every block runs it redundantly.
// Result deposited in shared (s_bin/s_rem) by the selecting thread.
__device__ __forceinline__ void scan_select_ro(const uint32_t* h, unsigned kneed,
                                               unsigned* ss, int tid,
                                               uint32_t* s_bin, int* s_rem) {
    unsigned local[NB/256];
    unsigned lsum = 0;
    if (tid < 256) {
#pragma unroll
        for (int i = 0; i < NB/256; i++) {
            local[i] = __ldcg(&h[tid * (NB/256) + i]);
            lsum += local[i];
        }
        ss[tid] = lsum;
    }
    __syncthreads();
    for (int off = 1; off < 256; off <<= 1) {
        unsigned n = (tid >= off && tid < 256) ? ss[tid - off] : 0u;
        __syncthreads();
        if (tid < 256) ss[tid] += n;
        __syncthreads();
    }
    if (tid < 256) {
        unsigned incl = ss[tid];
        unsigned excl = incl - lsum;
        if (excl < kneed && kneed <= incl) {
            unsigned cum = excl;
#pragma unroll
            for (int i = 0; i < NB/256; i++) {
                if (cum + local[i] >= kneed) {
                    *s_bin = (uint32_t)(tid * (NB/256) + i);
                    *s_rem = (int)(kneed - cum);
                    break;
                }
                cum += local[i];
            }
        }
    }
    __syncthreads();
}

// Ticket barrier: arrive, then poll until all BLKX row blocks arrived.
__device__ __forceinline__ void row_barrier(int* ticket, int tid) {
    __threadfence();
    if (tid == 0) {
        atomicAdd(ticket, 1);
        while (atomicAdd(ticket, 0) < BLKX) __nanosleep(128);
    }
    __syncthreads();
    __threadfence();   // acquire: order subsequent global reads
}

// ---------------- THE kernel: fused phases, redundant selects ---------------
__global__ void __launch_bounds__(THREADS, 1)
k_all(const float* __restrict__ in1, const float* __restrict__ in2,
      const float* __restrict__ in3, const int* __restrict__ tgt,
      const void* __restrict__ kdw_p, const void* __restrict__ forget_p,
      float* __restrict__ out)
{
    __shared__ uint32_t sh[NB];
    __shared__ unsigned ss[256];
    __shared__ double sd[32];
    __shared__ int    si[32];
    __shared__ int swt[32];
    __shared__ int s_last, s_c;
    __shared__ uint32_t s_bin; __shared__ int s_rem;

    int tid = threadIdx.x;
    const int row = blockIdx.y;
    for (int i = tid; i < NB; i += THREADS) sh[i] = 0u;
    __syncthreads();

    // ======================= PHASE 1: math + digit1 hist =====================
    const float kdw = (float)read_scalar(kdw_p);
    const float w   = 1.0f - kdw;

    const float4* b1a = (const float4*)(in1 + (size_t)row * 2 * NN);
    const float4* b1c = (const float4*)(in1 + (size_t)row * 2 * NN + NN);
    const float4* b2a = (const float4*)(in2 + (size_t)row * 2 * NN);
    const float4* b2c = (const float4*)(in2 + (size_t)row * 2 * NN + NN);
    const float4* b3a = (const float4*)(in3 + (size_t)row * 2 * NN);
    const float4* b3c = (const float4*)(in3 + (size_t)row * 2 * NN + NN);
    const int4*   bt  = (const int4*)(tgt + (size_t)row * NN);
    uint4* kout = (uint4*)(g_keys + (size_t)row * NN);
    uint4* pout = (uint4*)(g_pl3  + (size_t)row * NN);

    int tcnt = 0;

#pragma unroll 1
    for (int g = 0; g < 4; g++) {
        int vi = (blockIdx.x * CTILE + g * (THREADS*4)) / 4 + tid;
        float4 A1 = b1a[vi], C1 = b1c[vi];
        float4 A2 = b2a[vi], C2 = b2c[vi];
        float4 A3 = b3a[vi], C3 = b3c[vi];
        int4   T  = bt[vi];

        float ls0, ls1, ls2, ls3, l30, l31, l32, l33;
        pixel_loss(A1.x, C1.x, A2.x, C2.x, A3.x, C3.x, T.x, kdw, w, ls0, l30);
        pixel_loss(A1.y, C1.y, A2.y, C2.y, A3.y, C3.y, T.y, kdw, w, ls1, l31);
        pixel_loss(A1.z, C1.z, A2.z, C2.z, A3.z, C3.z, T.z, kdw, w, ls2, l32);
        pixel_loss(A1.w, C1.w, A2.w, C2.w, A3.w, C3.w, T.w, kdw, w, ls3, l33);

        uint4 K = make_uint4(f2mono(ls0), f2mono(ls1), f2mono(ls2), f2mono(ls3));
        kout[vi] = K;
        uint4 P = make_uint4(__float_as_uint(l30) | ((uint32_t)T.x << 31),
                             __float_as_uint(l31) | ((uint32_t)T.y << 31),
                             __float_as_uint(l32) | ((uint32_t)T.z << 31),
                             __float_as_uint(l33) | ((uint32_t)T.w << 31));
        pout[vi] = P;

        atomicAdd(&sh[K.x >> SH1], 1u);
        atomicAdd(&sh[K.y >> SH1], 1u);
        atomicAdd(&sh[K.z >> SH1], 1u);
        atomicAdd(&sh[K.w >> SH1], 1u);
        tcnt += T.x + T.y + T.z + T.w;
    }
    __syncthreads();
    for (int i = tid; i < NB; i += THREADS) {
        uint32_t v = sh[i];
        if (v) atomicAdd(&g_hist1[row * NB + i], v);
    }

#pragma unroll
    for (int o = 16; o; o >>= 1) tcnt += __shfl_down_sync(0xffffffffu, tcnt, o);
    if ((tid & 31) == 0) swt[tid >> 5] = tcnt;
    __syncthreads();
    if (tid == 0) {
        int s = 0;
#pragma unroll
        for (int i = 0; i < 32; i++) s += swt[i];
        atomicAdd(&g_ttotal, (unsigned long long)s);
        s_bin = 0; s_rem = 0;
    }

    // ---- barrier 1, then ALL blocks redundantly select digit1 ----
    row_barrier(&g_done1[row * PAD], tid);
    {
        double rem = 1.0 - read_scalar(forget_p);
        unsigned kneed = (unsigned)(rem * (double)NN);
        scan_select_ro(g_hist1 + row * NB, kneed, ss, tid, &s_bin, &s_rem);
    }
    uint32_t sel1   = s_bin;
    int      kneed1 = s_rem;
    __syncthreads();
    if (tid == 0) { s_bin = 0; s_rem = 0; }

    // ======================= PHASE 2: digit2 hist (L2-hot keys) ==============
    const uint4* keysv = (const uint4*)(g_keys + (size_t)row * NN);
    int vbase = blockIdx.x * (CTILE/4) + tid;
    {
        uint4 K0 = keysv[vbase];
        uint4 K1 = keysv[vbase + THREADS];
        uint4 K2 = keysv[vbase + 2*THREADS];
        uint4 K3 = keysv[vbase + 3*THREADS];
        uint32_t ks[16] = {K0.x,K0.y,K0.z,K0.w, K1.x,K1.y,K1.z,K1.w,
                           K2.x,K2.y,K2.z,K2.w, K3.x,K3.y,K3.z,K3.w};
#pragma unroll
        for (int j = 0; j < 16; j++)
            if ((ks[j] >> SH1) == sel1)
                atomicAdd(&g_hist2[row * NB + ((ks[j] >> SH2) & (NB-1))], 1u);
    }

    // ---- barrier 2, then ALL blocks redundantly select digit2 ----
    row_barrier(&g_done2[row * PAD], tid);
    scan_select_ro(g_hist2 + row * NB, (unsigned)kneed1, ss, tid, &s_bin, &s_rem);
    uint32_t thr    = ((sel1 << 11) | s_bin) << SH2;
    int      kneed2 = s_rem;
    uint32_t pfx22  = thr >> SH2;

    // ======================= PHASE 3: threshold sum + ties ===================
    const uint4* pl3v = (const uint4*)(g_pl3 + (size_t)row * NN);
    double sld = 0.0;
    int    st = 0;

#pragma unroll 1
    for (int it = 0; it < 4; it++) {
        uint4 K = keysv[vbase + it*THREADS];
        uint4 P = pl3v[vbase + it*THREADS];
        uint32_t ks4[4] = {K.x, K.y, K.z, K.w};
        uint32_t ps4[4] = {P.x, P.y, P.z, P.w};
        float sl = 0.0f;
#pragma unroll
        for (int j = 0; j < 4; j++) {
            if (ks4[j] < thr) {
                sl += __uint_as_float(ps4[j] & 0x7fffffffu);
                st += (int)(ps4[j] >> 31);
            } else if ((ks4[j] >> SH2) == pfx22) {   // tie bin (~tens per row)
                int p = atomicAdd(&g_eqcount[row], 1);
                if (p < EQCAP) {
                    g_eqkey[row * EQCAP + p] = ks4[j];
                    g_eqidx[row * EQCAP + p] = (uint32_t)((vbase + it*THREADS) * 4 + j);
                }
            }
        }
        sld += (double)sl;
    }
#pragma unroll
    for (int o = 16; o; o >>= 1) {
        sld += __shfl_down_sync(0xffffffffu, sld, o);
        st  += __shfl_down_sync(0xffffffffu, st, o);
    }
    if ((tid & 31) == 0) { sd[tid >> 5] = sld; si[tid >> 5] = st; }
    __syncthreads();
    if (tid == 0) {
        double S = 0.0; int Ti = 0;
#pragma unroll
        for (int i = 0; i < 32; i++) { S += sd[i]; Ti += si[i]; }
        atomicAdd(&g_sum_l3, S);
        atomicAdd(&g_sum_tsel, (unsigned long long)Ti);
    }

    // ---- last block of this row: tie resolve + cleanup + maybe output -------
    __threadfence();
    if (tid == 0) s_last = (atomicAdd(&g_done3[row * PAD], 1) == BLKX - 1);
    __syncthreads();
    if (!s_last) return;

    // broadcast tie count BEFORE resetting (race-fix discipline)
    if (tid == 0) s_c = min(__ldcg(&g_eqcount[row]), EQCAP);
    __syncthreads();
    int c = s_c;
    if (tid == 0) {
        g_eqcount[row] = 0;
        g_done1[row * PAD] = 0; g_done2[row * PAD] = 0; g_done3[row * PAD] = 0;
    }
    // zero both hist regions (restore zero-invariant)
    for (int i = tid; i < NB; i += THREADS) {
        g_hist1[row * NB + i] = 0u;
        g_hist2[row * NB + i] = 0u;
    }

    // reuse sh[] for the tie list (key, idx interleaved would exceed; use halves)
    __shared__ uint32_t tkey[EQCAP];
    __shared__ uint32_t tidx2[EQCAP];
    for (int i = tid; i < c; i += THREADS) {
        tkey[i]  = __ldcg(&g_eqkey[row * EQCAP + i]);
        tidx2[i] = __ldcg(&g_eqidx[row * EQCAP + i]);
    }
    __syncthreads();

    // exact rank-select by (key, idx) — stable-argsort equivalent
    double sl2 = 0.0;
    int    st2 = 0;
    for (int j = tid; j < c; j += THREADS) {
        uint32_t kj = tkey[j], ij = tidx2[j];
        int rank = 0;
        for (int q = 0; q < c; q++) {
            uint32_t kq = tkey[q], iq = tidx2[q];
            rank += (kq < kj || (kq == kj && iq < ij)) ? 1 : 0;
        }
        if (rank < kneed2) {
            uint32_t p = __ldcg(&g_pl3[(size_t)row * NN + ij]);
            sl2 += (double)__uint_as_float(p & 0x7fffffffu);
            st2 += (int)(p >> 31);
        }
    }
#pragma unroll
    for (int o = 16; o; o >>= 1) {
        sl2 += __shfl_down_sync(0xffffffffu, sl2, o);
        st2 += __shfl_down_sync(0xffffffffu, st2, o);
    }
    if ((tid & 31) == 0) { sd[tid >> 5] = sl2; si[tid >> 5] = st2; }
    __syncthreads();
    if (tid != 0) return;

    double S = 0.0; int Ti = 0;
#pragma unroll
    for (int i = 0; i < 32; i++) { S += sd[i]; Ti += si[i]; }
    atomicAdd(&g_sum_l3, S);
    atomicAdd(&g_sum_tsel, (unsigned long long)Ti);

    __threadfence();
    if (atomicAdd(&g_rows_done, 1) == BB - 1) {
        double sl = atomicAdd(&g_sum_l3, 0.0);
        unsigned long long ts = atomicAdd(&g_sum_tsel, 0ull);
        unsigned long long tt = atomicAdd(&g_ttotal, 0ull);
        double rem = 1.0 - read_scalar(forget_p);
        long long num_rem = (long long)(rem * (double)NN);
        double denom = (double)BB * (double)num_rem;
        out[0] = (float)(sl / denom);
        out[1] = (float)((double)ts / (double)tt);
        // restore zero-invariant for graph replays
        g_rows_done = 0;
        g_sum_l3    = 0.0;
        g_sum_tsel  = 0ull;
        g_ttotal    = 0ull;
    }
}

// ---------------- host entry ----------------
extern "C" void kernel_launch(void* const* d_in, const int* in_sizes, int n_in,
                              void* d_out, int out_size) {
    const float* in1    = (const float*)d_in[0];
    const float* in2    = (const float*)d_in[1];
    const float* in3    = (const float*)d_in[2];
    const int*   tgt    = (const int*)d_in[3];
    const void*  forget = d_in[4];
    const void*  kdw    = d_in[5];
    float* out = (float*)d_out;

    k_all<<<dim3(BLKX, BB), THREADS>>>(in1, in2, in3, tgt, kdw, forget, out);

    (void)in_sizes; (void)n_in; (void)out_size;
}